// round 16
// baseline (speedup 1.0000x reference)
#include <cuda_runtime.h>
#include <cuda_fp16.h>
#include <cstdint>

#define B_   8192
#define D_   1024
#define H_   1024
#define E_   8
#define KC   5
#define KM1  4
#define EPS_ 1e-8f

// ---------------- PTX helpers (sm_80-era; tcgen05 unavailable on this toolchain path) ----------------
__device__ __forceinline__ uint32_t smem_u32(const void* p) {
    uint32_t a;
    asm("{ .reg .u64 t; cvta.to.shared.u64 t, %1; cvt.u32.u64 %0, t; }" : "=r"(a) : "l"(p));
    return a;
}
__device__ __forceinline__ void cp16(uint32_t saddr, const void* g) {
    asm volatile("cp.async.cg.shared.global [%0], [%1], 16;" :: "r"(saddr), "l"(g));
}
#define CP_COMMIT() asm volatile("cp.async.commit_group;" ::: "memory")
#define CP_WAIT(N)  asm volatile("cp.async.wait_group %0;" :: "n"(N) : "memory")

__device__ __forceinline__ void ldsm4(uint32_t& r0, uint32_t& r1, uint32_t& r2, uint32_t& r3,
                                      uint32_t addr) {
    asm volatile("ldmatrix.sync.aligned.m8n8.x4.shared.b16 {%0,%1,%2,%3}, [%4];"
                 : "=r"(r0), "=r"(r1), "=r"(r2), "=r"(r3) : "r"(addr));
}
__device__ __forceinline__ void mma16816(float* c, const uint32_t* a, const uint32_t* b) {
    asm volatile(
        "mma.sync.aligned.m16n8k16.row.col.f32.f16.f16.f32 "
        "{%0,%1,%2,%3},{%4,%5,%6,%7},{%8,%9},{%0,%1,%2,%3};"
        : "+f"(c[0]), "+f"(c[1]), "+f"(c[2]), "+f"(c[3])
        : "r"(a[0]), "r"(a[1]), "r"(a[2]), "r"(a[3]), "r"(b[0]), "r"(b[1]));
}
__device__ __forceinline__ int atom_acqrel_add(int* p, int v) {
    int old;
    asm volatile("atom.acq_rel.gpu.add.s32 %0, [%1], %2;"
                 : "=r"(old) : "l"(p), "r"(v) : "memory");
    return old;
}

// ---------------- scratch ----------------
__device__ int    g_off[E_ + 1];
__device__ int    g_tok[B_];
__device__ int    g_is64;
__device__ int    g_arr[E_ * 64];                 // split-n finalize semaphores
__device__ __half g_x[(size_t)B_ * D_];           // x fp16, TOKEN order
__device__ __half g_w[(size_t)E_ * H_ * D_];      // W1^T fp16 [e][n][k]
__device__ float  g_plog[(size_t)16 * B_ * 4];    // partial logits per n-tile (16 slots)

// ---------------- fused prologue: route (block 0) + convert_x + convert_w ----------------
#define NXB 2048                                   // x-convert blocks (16 floats/thread)
#define NWB 2048                                   // w-transpose blocks (4 tiles of 32x32)

__global__ __launch_bounds__(256) void k_prep(const float* __restrict__ x,
                                              const float* __restrict__ W1,
                                              const int* __restrict__ sidx) {
    __shared__ float s[32][33];
    __shared__ int s_any, s_cnt[E_], s_pos[E_], s_off[E_ + 1];
    const int t = threadIdx.x;
    int bid = blockIdx.x;

    if (bid == 0) {
        // ---- routing ----
        if (t == 0) s_any = 0;
        if (t < E_) { s_cnt[t] = 0; s_pos[t] = 0; }
        for (int i = t; i < E_ * 64; i += 256) g_arr[i] = 0;
        __syncthreads();
        int any = 0;
        for (int i = t; i < B_ / 2; i += 256)
            if (sidx[2 * i + 1] != 0) any = 1;
        if (any) atomicOr(&s_any, 1);
        __syncthreads();
        const int is64 = (s_any == 0) ? 1 : 0;
        if (t == 0) g_is64 = is64;
#pragma unroll
        for (int j = 0; j < 32; j++) {
            int b = t + j * 256;
            int e = is64 ? sidx[2 * b] : sidx[b];
            atomicAdd(&s_cnt[e], 1);
        }
        __syncthreads();
        if (t == 0) {
            int acc = 0;
            for (int e = 0; e < E_; e++) { s_off[e] = acc; acc += s_cnt[e]; }
            s_off[E_] = acc;
        }
        __syncthreads();
        if (t <= E_) g_off[t] = s_off[t];
#pragma unroll
        for (int j = 0; j < 32; j++) {
            int b = t + j * 256;
            int e = is64 ? sidx[2 * b] : sidx[b];
            int p = s_off[e] + atomicAdd(&s_pos[e], 1);
            g_tok[p] = b;
        }
        return;
    }
    bid -= 1;
    if (bid < NXB) {
        // ---- x fp32 -> fp16 streaming convert (16 floats/thread) ----
        size_t base = (size_t)bid * 4096 + t * 4;
#pragma unroll
        for (int j = 0; j < 4; j++) {
            size_t i = base + (size_t)j * 1024;
            float4 v = *(const float4*)(x + i);
            *(__half2*)(g_x + i)     = __halves2half2(__float2half(v.x), __float2half(v.y));
            *(__half2*)(g_x + i + 2) = __halves2half2(__float2half(v.z), __float2half(v.w));
        }
        return;
    }
    // ---- W1[e][k][n] -> g_w[e][n][k] fp16 transpose, 4 tiles of 32x32 ----
    int tx = t & 31, ty = t >> 5;   // (32, 8)
    int t0 = (bid - NXB) * 4;
#pragma unroll
    for (int tt = 0; tt < 4; tt++) {
        int tile = t0 + tt;
        int e  = tile >> 10;
        int k0 = ((tile >> 5) & 31) * 32;
        int n0 = (tile & 31) * 32;
        const float* src = W1 + (size_t)e * D_ * H_;
#pragma unroll
        for (int r = 0; r < 4; r++)
            s[ty + 8 * r][tx] = src[(size_t)(k0 + ty + 8 * r) * H_ + n0 + tx];
        __syncthreads();
#pragma unroll
        for (int r = 0; r < 4; r++) {
            int n = n0 + ty + 8 * r, k = k0 + tx;
            g_w[((size_t)e << 20) + (size_t)n * D_ + k] = __float2half(s[tx][ty + 8 * r]);
        }
        __syncthreads();
    }
}

// ---------------- GEMM1 (fp16) + fused GEMM2 + split-n finalize ----------------
// CTA 128(m) x 64(n), 8 warps = (2m x 2n x 2k-split). Every warp runs the EXACT
// R12 inner pattern (warp 64x32: 4 A-ldsm + 2 W-ldsm + 16 MMA per k16). wk pairs
// cover disjoint k-halves of each BK=64 chunk; partial pre-activation sums are
// combined via smem before ReLU. 1024 active tiles kills quantization.
#define BK       64
#define ROW_B    144
#define TILEA_SB (128 * ROW_B)             // 18432
#define TILEW_SB (64 * ROW_B)              // 9216
#define STAGE_B  (TILEA_SB + TILEW_SB)     // 27648
#define DSMEM_B  (2 * STAGE_B)             // 55296  (also reused for k-sum exchange: 32KB)

__global__ __launch_bounds__(256, 2) void k_gemm1(const float* __restrict__ b1,
                                                  const float* __restrict__ W2,
                                                  const float* __restrict__ b2,
                                                  float* __restrict__ out, int out_size) {
    const int e   = blockIdx.z;
    const int off = g_off[e];
    const int cnt = g_off[e + 1] - off;
    const int mb  = blockIdx.y;
    const int m0  = mb * 128;
    if (m0 >= cnt) return;
    const int bx  = blockIdx.x;       // n-tile 0..15
    const int n0  = bx * 64;

    extern __shared__ char dsm[];
    __shared__ float  s_bias[64];
    __shared__ float4 s_w2[64];
    __shared__ float  s_part[2][128][4];
    __shared__ int    s_fin;

    const int tid = threadIdx.x, wid = tid >> 5, l = tid & 31;
    // warps 0-3: wk=0 (tid<128, contiguous); warps 4-7: wk=1
    const int wk = wid >> 2;
    const int wm = (wid >> 1) & 1, wn = wid & 1;
    const uint32_t sbase = smem_u32(dsm);

    if (tid < 64) {
        s_bias[tid] = b1[e * H_ + n0 + tid];
        s_w2[tid]   = *(const float4*)(W2 + ((size_t)e * H_ + n0 + tid) * KM1);
    }

    // A: 1024 granules of 16B (128 rows x 8 segs), 4/thread.  W: 512 granules (64 rows), 2/thread.
    uint32_t a_sm[4], w_sm[2];
    size_t   a_g[4], w_g[2];
#pragma unroll
    for (int j = 0; j < 4; j++) {
        int g   = tid + 256 * j;
        int row = g >> 3, kg = g & 7;
        a_sm[j] = (uint32_t)(row * ROW_B + kg * 16);
        int gm  = min(m0 + row, cnt - 1);
        a_g[j]  = (size_t)g_tok[off + gm] * D_ + kg * 8;
    }
#pragma unroll
    for (int j = 0; j < 2; j++) {
        int g   = tid + 256 * j;
        int row = g >> 3, kg = g & 7;
        w_sm[j] = (uint32_t)(TILEA_SB + row * ROW_B + kg * 16);
        w_g[j]  = ((size_t)e << 20) + (size_t)(n0 + row) * D_ + kg * 8;
    }

    float acc[4][4][4];
#pragma unroll
    for (int i = 0; i < 4; i++)
#pragma unroll
        for (int j = 0; j < 4; j++)
#pragma unroll
            for (int q = 0; q < 4; q++) acc[i][j][q] = 0.f;

    // per-warp lane offsets; wk selects the 32-half (64 bytes) of each BK=64 chunk
    const uint32_t a_loff = (uint32_t)((wm * 64 + (l & 15)) * ROW_B + ((l & 16) >> 1) * 2 + wk * 64);
    const uint32_t b_loff = (uint32_t)(TILEA_SB +
                                       (wn * 32 + (l & 7) + ((l & 16) >> 1)) * ROW_B + (l & 8) * 2 + wk * 64);

    const int NIT = D_ / BK;   // 16

#pragma unroll
    for (int j = 0; j < 4; j++) cp16(sbase + a_sm[j], g_x + a_g[j]);
#pragma unroll
    for (int j = 0; j < 2; j++) cp16(sbase + w_sm[j], g_w + w_g[j]);
    CP_COMMIT();

    for (int it = 0; it < NIT; ++it) {
        if (it + 1 < NIT) {
            const int kt = (it + 1) * BK;
            uint32_t st = sbase + ((it + 1) & 1) * STAGE_B;
#pragma unroll
            for (int j = 0; j < 4; j++) cp16(st + a_sm[j], g_x + a_g[j] + kt);
#pragma unroll
            for (int j = 0; j < 2; j++) cp16(st + w_sm[j], g_w + w_g[j] + kt);
            CP_COMMIT();
            CP_WAIT(1);
        } else {
            CP_WAIT(0);
        }
        __syncthreads();

        const uint32_t sg = sbase + (it & 1) * STAGE_B;
        const uint32_t sA = sg + a_loff;
        const uint32_t sW = sg + b_loff;

        // warp's 32-half split into 2 k16 steps (identical mix to the proven 128x128 kernel)
#pragma unroll
        for (int ks = 0; ks < 2; ++ks) {
            uint32_t ar[4][4], wf[2][4];
#pragma unroll
            for (int mt = 0; mt < 4; mt++) {
                uint32_t ao = (uint32_t)(mt * 16 * ROW_B + ks * 32);
                ldsm4(ar[mt][0], ar[mt][1], ar[mt][2], ar[mt][3], sA + ao);
            }
#pragma unroll
            for (int nt = 0; nt < 2; nt++) {
                uint32_t bo = (uint32_t)(nt * 16 * ROW_B + ks * 32);
                ldsm4(wf[nt][0], wf[nt][1], wf[nt][2], wf[nt][3], sW + bo);
            }
#pragma unroll
            for (int mt = 0; mt < 4; mt++) {
#pragma unroll
                for (int j = 0; j < 4; j++) {
                    mma16816(acc[mt][j], ar[mt], &wf[j >> 1][(j & 1) * 2]);
                }
            }
        }
        __syncthreads();
    }

    // ---- k-split reduce: wk=1 warps park acc in (dead) stage smem; wk=0 warps add ----
    {
        float4* xb = (float4*)dsm;   // 128 slots x 64 floats = 32KB < DSMEM_B
        if (wk == 1) {
            float4* dst = xb + (size_t)(tid - 128) * 16;
#pragma unroll
            for (int mt = 0; mt < 4; mt++)
#pragma unroll
                for (int j = 0; j < 4; j++)
                    dst[mt * 4 + j] = *(float4*)acc[mt][j];
        }
        __syncthreads();
        if (wk == 0) {
            float4* src = xb + (size_t)tid * 16;
#pragma unroll
            for (int mt = 0; mt < 4; mt++)
#pragma unroll
                for (int j = 0; j < 4; j++) {
                    float4 v = src[mt * 4 + j];
                    acc[mt][j][0] += v.x; acc[mt][j][1] += v.y;
                    acc[mt][j][2] += v.z; acc[mt][j][3] += v.w;
                }
        }
    }

    // ---- fused epilogue (wk=0 warps, tid<128): h = relu(acc + b1); pl = h @ W2 ----
    if (wk == 0) {
        float pl[4][2][4];
#pragma unroll
        for (int mt = 0; mt < 4; mt++)
#pragma unroll
            for (int g = 0; g < 2; g++)
#pragma unroll
                for (int k = 0; k < 4; k++) pl[mt][g][k] = 0.f;

#pragma unroll
        for (int mt = 0; mt < 4; mt++) {
#pragma unroll
            for (int j = 0; j < 4; j++) {
                int nb = wn * 32 + j * 8 + (l & 3) * 2;
                float4 w20 = s_w2[nb], w21 = s_w2[nb + 1];
                float bx0 = s_bias[nb], bx1 = s_bias[nb + 1];
                float h00 = fmaxf(acc[mt][j][0] + bx0, 0.f);
                float h01 = fmaxf(acc[mt][j][1] + bx1, 0.f);
                float h10 = fmaxf(acc[mt][j][2] + bx0, 0.f);
                float h11 = fmaxf(acc[mt][j][3] + bx1, 0.f);
                pl[mt][0][0] += h00 * w20.x + h01 * w21.x;
                pl[mt][0][1] += h00 * w20.y + h01 * w21.y;
                pl[mt][0][2] += h00 * w20.z + h01 * w21.z;
                pl[mt][0][3] += h00 * w20.w + h01 * w21.w;
                pl[mt][1][0] += h10 * w20.x + h11 * w21.x;
                pl[mt][1][1] += h10 * w20.y + h11 * w21.y;
                pl[mt][1][2] += h10 * w20.z + h11 * w21.z;
                pl[mt][1][3] += h10 * w20.w + h11 * w21.w;
            }
        }
#pragma unroll
        for (int mt = 0; mt < 4; mt++)
#pragma unroll
            for (int g = 0; g < 2; g++)
#pragma unroll
                for (int k = 0; k < 4; k++) {
                    float v = pl[mt][g][k];
                    v += __shfl_xor_sync(0xffffffffu, v, 1);
                    v += __shfl_xor_sync(0xffffffffu, v, 2);
                    pl[mt][g][k] = v;
                }
        if ((l & 3) == 0) {
            int r = l >> 2;
#pragma unroll
            for (int mt = 0; mt < 4; mt++)
#pragma unroll
                for (int g = 0; g < 2; g++) {
                    int row = wm * 64 + mt * 16 + r + g * 8;
#pragma unroll
                    for (int k = 0; k < 4; k++) s_part[wn][row][k] = pl[mt][g][k];
                }
        }
    }
    __syncthreads();
    if (tid < 128) {
        int m = m0 + tid;
        if (m < cnt) {
            float4 s;
            s.x = s_part[0][tid][0] + s_part[1][tid][0];
            s.y = s_part[0][tid][1] + s_part[1][tid][1];
            s.z = s_part[0][tid][2] + s_part[1][tid][2];
            s.w = s_part[0][tid][3] + s_part[1][tid][3];
            *(float4*)(g_plog + ((size_t)bx * B_ + off + m) * 4) = s;
        }
    }
    // ---- split-n finalize: last of 16 n-tiles reduces + softmax + writes out ----
    __syncthreads();
    if (tid == 0) s_fin = (atom_acqrel_add(&g_arr[e * 64 + mb], 1) == 15) ? 1 : 0;
    __syncthreads();
    if (!s_fin) return;
    if (tid < 128) {
        int m = m0 + tid;
        if (m >= cnt) return;
        float4 a = make_float4(0.f, 0.f, 0.f, 0.f);
#pragma unroll
        for (int s = 0; s < 16; s++) {
            float4 v = *(const float4*)(g_plog + ((size_t)s * B_ + off + m) * 4);
            a.x += v.x; a.y += v.y; a.z += v.z; a.w += v.w;
        }
        int tok = g_tok[off + m];
        float lg[KM1];
        lg[0] = a.x + b2[e * KM1 + 0];
        lg[1] = a.y + b2[e * KM1 + 1];
        lg[2] = a.z + b2[e * KM1 + 2];
        lg[3] = a.w + b2[e * KM1 + 3];
        float q[KM1];
#pragma unroll
        for (int k = 0; k < KM1; k++) q[k] = 1.f / (1.f + expf(-lg[k]));
        float p[KC];
        p[0] = 1.f - q[0];
        p[1] = q[0] - q[1];
        p[2] = q[1] - q[2];
        p[3] = q[2] - q[3];
        p[4] = q[3];
        float s = 0.f;
#pragma unroll
        for (int k = 0; k < KC; k++) { p[k] = fmaxf(p[k], EPS_); s += p[k]; }
        s = fmaxf(s, EPS_);
        float inv = 1.f / s;
#pragma unroll
        for (int k = 0; k < KC; k++) p[k] *= inv;

        if (out_size >= B_ * (KM1 + KC)) {
#pragma unroll
            for (int k = 0; k < KM1; k++) out[(size_t)tok * KM1 + k] = lg[k];
#pragma unroll
            for (int k = 0; k < KC; k++)  out[(size_t)B_ * KM1 + (size_t)tok * KC + k] = p[k];
        } else if (out_size == B_ * KC) {
#pragma unroll
            for (int k = 0; k < KC; k++)  out[(size_t)tok * KC + k] = p[k];
        } else {
#pragma unroll
            for (int k = 0; k < KM1; k++) out[(size_t)tok * KM1 + k] = lg[k];
        }
    }
}

// ---------------- launch: exactly 2 kernels, hard-serialized ----------------
extern "C" void kernel_launch(void* const* d_in, const int* in_sizes, int n_in,
                              void* d_out, int out_size) {
    const float* x    = (const float*)d_in[0];
    const int*   sidx = (const int*)  d_in[1];
    const float* W1   = (const float*)d_in[2];
    const float* b1   = (const float*)d_in[3];
    const float* W2   = (const float*)d_in[4];
    const float* b2   = (const float*)d_in[5];
    float*       out  = (float*)d_out;

    static bool init_done = false;
    if (!init_done) {
        cudaFuncSetAttribute(k_gemm1, cudaFuncAttributeMaxDynamicSharedMemorySize, DSMEM_B);
        init_done = true;
    }

    k_prep<<<1 + NXB + NWB, 256>>>(x, W1, sidx);
    k_gemm1<<<dim3(16, B_ / 128, E_), 256, DSMEM_B>>>(b1, W2, b2, out, out_size);
}

// round 17
// speedup vs baseline: 1.4530x; 1.4530x over previous
#include <cuda_runtime.h>
#include <cuda_fp16.h>
#include <cstdint>

#define B_   8192
#define D_   1024
#define H_   1024
#define E_   8
#define KC   5
#define KM1  4
#define EPS_ 1e-8f

// ---------------- PTX helpers (sm_80-era; tcgen05 unavailable on this toolchain path) ----------------
__device__ __forceinline__ uint32_t smem_u32(const void* p) {
    uint32_t a;
    asm("{ .reg .u64 t; cvta.to.shared.u64 t, %1; cvt.u32.u64 %0, t; }" : "=r"(a) : "l"(p));
    return a;
}
__device__ __forceinline__ void cp16(uint32_t saddr, const void* g) {
    asm volatile("cp.async.cg.shared.global [%0], [%1], 16;" :: "r"(saddr), "l"(g));
}
#define CP_COMMIT() asm volatile("cp.async.commit_group;" ::: "memory")
#define CP_WAIT(N)  asm volatile("cp.async.wait_group %0;" :: "n"(N) : "memory")

__device__ __forceinline__ void ldsm4(uint32_t& r0, uint32_t& r1, uint32_t& r2, uint32_t& r3,
                                      uint32_t addr) {
    asm volatile("ldmatrix.sync.aligned.m8n8.x4.shared.b16 {%0,%1,%2,%3}, [%4];"
                 : "=r"(r0), "=r"(r1), "=r"(r2), "=r"(r3) : "r"(addr));
}
__device__ __forceinline__ void mma16816(float* c, const uint32_t* a, const uint32_t* b) {
    asm volatile(
        "mma.sync.aligned.m16n8k16.row.col.f32.f16.f16.f32 "
        "{%0,%1,%2,%3},{%4,%5,%6,%7},{%8,%9},{%0,%1,%2,%3};"
        : "+f"(c[0]), "+f"(c[1]), "+f"(c[2]), "+f"(c[3])
        : "r"(a[0]), "r"(a[1]), "r"(a[2]), "r"(a[3]), "r"(b[0]), "r"(b[1]));
}
__device__ __forceinline__ int atom_acqrel_add(int* p, int v) {
    int old;
    asm volatile("atom.acq_rel.gpu.add.s32 %0, [%1], %2;"
                 : "=r"(old) : "l"(p), "r"(v) : "memory");
    return old;
}

// ---------------- scratch ----------------
__device__ int    g_off[E_ + 1];
__device__ int    g_tok[B_];
__device__ int    g_is64;
__device__ int    g_arr[E_ * 64];                 // split-n finalize semaphores
__device__ __half g_x[(size_t)B_ * D_];           // x fp16, TOKEN order
__device__ __half g_w[(size_t)E_ * H_ * D_];      // W1^T fp16 [e][n][k]
__device__ float  g_plog[(size_t)8 * B_ * 4];     // partial logits per n-tile

// ---------------- fused prologue: route (block 0) + convert_x + convert_w ----------------
#define NXB 2048                                   // x-convert blocks (16 floats/thread)
#define NWB 2048                                   // w-transpose blocks (4 tiles of 32x32)

__global__ __launch_bounds__(256) void k_prep(const float* __restrict__ x,
                                              const float* __restrict__ W1,
                                              const int* __restrict__ sidx) {
    __shared__ float s[32][33];
    __shared__ int s_any, s_cnt[E_], s_pos[E_], s_off[E_ + 1];
    const int t = threadIdx.x;
    int bid = blockIdx.x;

    if (bid == 0) {
        // ---- routing ----
        if (t == 0) s_any = 0;
        if (t < E_) { s_cnt[t] = 0; s_pos[t] = 0; }
        for (int i = t; i < E_ * 64; i += 256) g_arr[i] = 0;
        __syncthreads();
        int any = 0;
        for (int i = t; i < B_ / 2; i += 256)
            if (sidx[2 * i + 1] != 0) any = 1;
        if (any) atomicOr(&s_any, 1);
        __syncthreads();
        const int is64 = (s_any == 0) ? 1 : 0;
        if (t == 0) g_is64 = is64;
#pragma unroll
        for (int j = 0; j < 32; j++) {
            int b = t + j * 256;
            int e = is64 ? sidx[2 * b] : sidx[b];
            atomicAdd(&s_cnt[e], 1);
        }
        __syncthreads();
        if (t == 0) {
            int acc = 0;
            for (int e = 0; e < E_; e++) { s_off[e] = acc; acc += s_cnt[e]; }
            s_off[E_] = acc;
        }
        __syncthreads();
        if (t <= E_) g_off[t] = s_off[t];
#pragma unroll
        for (int j = 0; j < 32; j++) {
            int b = t + j * 256;
            int e = is64 ? sidx[2 * b] : sidx[b];
            int p = s_off[e] + atomicAdd(&s_pos[e], 1);
            g_tok[p] = b;
        }
        return;
    }
    bid -= 1;
    if (bid < NXB) {
        // ---- x fp32 -> fp16 streaming convert (16 floats/thread, evict-first reads) ----
        size_t base = (size_t)bid * 4096 + t * 4;
#pragma unroll
        for (int j = 0; j < 4; j++) {
            size_t i = base + (size_t)j * 1024;
            float4 v = __ldcs((const float4*)(x + i));
            *(__half2*)(g_x + i)     = __halves2half2(__float2half(v.x), __float2half(v.y));
            *(__half2*)(g_x + i + 2) = __halves2half2(__float2half(v.z), __float2half(v.w));
        }
        return;
    }
    // ---- W1[e][k][n] -> g_w[e][n][k] fp16 transpose, 4 tiles of 32x32 ----
    int tx = t & 31, ty = t >> 5;   // (32, 8)
    int t0 = (bid - NXB) * 4;
#pragma unroll
    for (int tt = 0; tt < 4; tt++) {
        int tile = t0 + tt;
        int e  = tile >> 10;
        int k0 = ((tile >> 5) & 31) * 32;
        int n0 = (tile & 31) * 32;
        const float* src = W1 + (size_t)e * D_ * H_;
#pragma unroll
        for (int r = 0; r < 4; r++)
            s[ty + 8 * r][tx] = __ldcs(&src[(size_t)(k0 + ty + 8 * r) * H_ + n0 + tx]);
        __syncthreads();
#pragma unroll
        for (int r = 0; r < 4; r++) {
            int n = n0 + ty + 8 * r, k = k0 + tx;
            g_w[((size_t)e << 20) + (size_t)n * D_ + k] = __float2half(s[tx][ty + 8 * r]);
        }
        __syncthreads();
    }
}

// ---------------- GEMM1 (fp16) + fused GEMM2 + split-n finalize (R12 core, proven 66us) ----------------
// CTA 128x128, 8 warps (2m x 4n, warp 64x32), BK=64, double-buffered cp.async, 2 CTAs/SM.
#define BK       64
#define ROW_B    144
#define TILE_SB  (128 * ROW_B)             // 18432
#define STAGE_B  (2 * TILE_SB)
#define DSMEM_B  (2 * STAGE_B)             // 73728

__global__ __launch_bounds__(256, 2) void k_gemm1(const float* __restrict__ b1,
                                                  const float* __restrict__ W2,
                                                  const float* __restrict__ b2,
                                                  float* __restrict__ out, int out_size) {
    const int e   = blockIdx.z;
    const int off = g_off[e];
    const int cnt = g_off[e + 1] - off;
    const int mb  = blockIdx.y;
    const int m0  = mb * 128;
    if (m0 >= cnt) return;
    const int bx  = blockIdx.x;       // n-tile 0..7
    const int n0  = bx * 128;

    extern __shared__ char dsm[];
    __shared__ float  s_bias[128];
    __shared__ float4 s_w2[128];
    __shared__ float  s_part[4][128][4];
    __shared__ int    s_fin;

    const int tid = threadIdx.x, wid = tid >> 5, l = tid & 31;
    const int wm = wid >> 2, wn = wid & 3;
    const uint32_t sbase = smem_u32(dsm);

    if (tid < 128) {
        s_bias[tid] = b1[e * H_ + n0 + tid];
        s_w2[tid]   = *(const float4*)(W2 + ((size_t)e * H_ + n0 + tid) * KM1);
    }

    uint32_t sm_off[4];
    size_t   a_g[4], b_g[4];
#pragma unroll
    for (int j = 0; j < 4; j++) {
        int g   = tid + 256 * j;
        int row = g >> 3, kg = g & 7;
        sm_off[j] = (uint32_t)(row * ROW_B + kg * 16);
        int gm  = min(m0 + row, cnt - 1);
        a_g[j]  = (size_t)g_tok[off + gm] * D_ + kg * 8;
        b_g[j]  = ((size_t)e << 20) + (size_t)(n0 + row) * D_ + kg * 8;
    }

    float acc[4][4][4];
#pragma unroll
    for (int i = 0; i < 4; i++)
#pragma unroll
        for (int j = 0; j < 4; j++)
#pragma unroll
            for (int q = 0; q < 4; q++) acc[i][j][q] = 0.f;

    const uint32_t a_loff = (uint32_t)((wm * 64 + (l & 15)) * ROW_B + ((l & 16) >> 1) * 2);
    const uint32_t b_loff = (uint32_t)((wn * 32 + (l & 7) + ((l & 16) >> 1)) * ROW_B + (l & 8) * 2);

    const int NIT = D_ / BK;   // 16

#pragma unroll
    for (int j = 0; j < 4; j++) {
        uint32_t s = sbase + sm_off[j];
        cp16(s + 0 * TILE_SB, g_x + a_g[j]);
        cp16(s + 1 * TILE_SB, g_w + b_g[j]);
    }
    CP_COMMIT();

    for (int it = 0; it < NIT; ++it) {
        if (it + 1 < NIT) {
            const int kt = (it + 1) * BK;
            uint32_t st = sbase + ((it + 1) & 1) * STAGE_B;
#pragma unroll
            for (int j = 0; j < 4; j++) {
                uint32_t s = st + sm_off[j];
                cp16(s + 0 * TILE_SB, g_x + a_g[j] + kt);
                cp16(s + 1 * TILE_SB, g_w + b_g[j] + kt);
            }
            CP_COMMIT();
            CP_WAIT(1);
        } else {
            CP_WAIT(0);
        }
        __syncthreads();

        const uint32_t sg = sbase + (it & 1) * STAGE_B;
        const uint32_t sA = sg + 0 * TILE_SB + a_loff;
        const uint32_t sW = sg + 1 * TILE_SB + b_loff;

#pragma unroll
        for (int ks = 0; ks < BK / 16; ++ks) {
            uint32_t ar[4][4], wf[2][4];
#pragma unroll
            for (int mt = 0; mt < 4; mt++) {
                uint32_t ao = (uint32_t)(mt * 16 * ROW_B + ks * 32);
                ldsm4(ar[mt][0], ar[mt][1], ar[mt][2], ar[mt][3], sA + ao);
            }
#pragma unroll
            for (int nt = 0; nt < 2; nt++) {
                uint32_t bo = (uint32_t)(nt * 16 * ROW_B + ks * 32);
                ldsm4(wf[nt][0], wf[nt][1], wf[nt][2], wf[nt][3], sW + bo);
            }
#pragma unroll
            for (int mt = 0; mt < 4; mt++) {
#pragma unroll
                for (int j = 0; j < 4; j++) {
                    mma16816(acc[mt][j], ar[mt], &wf[j >> 1][(j & 1) * 2]);
                }
            }
        }
        __syncthreads();
    }

    // ---- fused epilogue: h = relu(acc + b1); partial logits = h_slab @ W2_block ----
    float pl[4][2][4];
#pragma unroll
    for (int mt = 0; mt < 4; mt++)
#pragma unroll
        for (int g = 0; g < 2; g++)
#pragma unroll
            for (int k = 0; k < 4; k++) pl[mt][g][k] = 0.f;

#pragma unroll
    for (int mt = 0; mt < 4; mt++) {
#pragma unroll
        for (int j = 0; j < 4; j++) {
            int nb = wn * 32 + j * 8 + (l & 3) * 2;
            float4 w20 = s_w2[nb], w21 = s_w2[nb + 1];
            float bx0 = s_bias[nb], bx1 = s_bias[nb + 1];
            float h00 = fmaxf(acc[mt][j][0] + bx0, 0.f);
            float h01 = fmaxf(acc[mt][j][1] + bx1, 0.f);
            float h10 = fmaxf(acc[mt][j][2] + bx0, 0.f);
            float h11 = fmaxf(acc[mt][j][3] + bx1, 0.f);
            pl[mt][0][0] += h00 * w20.x + h01 * w21.x;
            pl[mt][0][1] += h00 * w20.y + h01 * w21.y;
            pl[mt][0][2] += h00 * w20.z + h01 * w21.z;
            pl[mt][0][3] += h00 * w20.w + h01 * w21.w;
            pl[mt][1][0] += h10 * w20.x + h11 * w21.x;
            pl[mt][1][1] += h10 * w20.y + h11 * w21.y;
            pl[mt][1][2] += h10 * w20.z + h11 * w21.z;
            pl[mt][1][3] += h10 * w20.w + h11 * w21.w;
        }
    }
#pragma unroll
    for (int mt = 0; mt < 4; mt++)
#pragma unroll
        for (int g = 0; g < 2; g++)
#pragma unroll
            for (int k = 0; k < 4; k++) {
                float v = pl[mt][g][k];
                v += __shfl_xor_sync(0xffffffffu, v, 1);
                v += __shfl_xor_sync(0xffffffffu, v, 2);
                pl[mt][g][k] = v;
            }
    if ((l & 3) == 0) {
        int r = l >> 2;
#pragma unroll
        for (int mt = 0; mt < 4; mt++)
#pragma unroll
            for (int g = 0; g < 2; g++) {
                int row = wm * 64 + mt * 16 + r + g * 8;
#pragma unroll
                for (int k = 0; k < 4; k++) s_part[wn][row][k] = pl[mt][g][k];
            }
    }
    __syncthreads();
    if (tid < 128) {
        int m = m0 + tid;
        if (m < cnt) {
            float4 s;
            s.x = s_part[0][tid][0] + s_part[1][tid][0] + s_part[2][tid][0] + s_part[3][tid][0];
            s.y = s_part[0][tid][1] + s_part[1][tid][1] + s_part[2][tid][1] + s_part[3][tid][1];
            s.z = s_part[0][tid][2] + s_part[1][tid][2] + s_part[2][tid][2] + s_part[3][tid][2];
            s.w = s_part[0][tid][3] + s_part[1][tid][3] + s_part[2][tid][3] + s_part[3][tid][3];
            *(float4*)(g_plog + ((size_t)bx * B_ + off + m) * 4) = s;
        }
    }
    // ---- split-n finalize (semaphore: bar.sync -> tid0 acq_rel atomic -> bar.sync) ----
    __syncthreads();
    if (tid == 0) s_fin = (atom_acqrel_add(&g_arr[e * 64 + mb], 1) == 7) ? 1 : 0;
    __syncthreads();
    if (!s_fin) return;
    if (tid < 128) {
        int m = m0 + tid;
        if (m >= cnt) return;
        float4 a = make_float4(0.f, 0.f, 0.f, 0.f);
#pragma unroll
        for (int s = 0; s < 8; s++) {
            float4 v = *(const float4*)(g_plog + ((size_t)s * B_ + off + m) * 4);
            a.x += v.x; a.y += v.y; a.z += v.z; a.w += v.w;
        }
        int tok = g_tok[off + m];
        float lg[KM1];
        lg[0] = a.x + b2[e * KM1 + 0];
        lg[1] = a.y + b2[e * KM1 + 1];
        lg[2] = a.z + b2[e * KM1 + 2];
        lg[3] = a.w + b2[e * KM1 + 3];
        float q[KM1];
#pragma unroll
        for (int k = 0; k < KM1; k++) q[k] = 1.f / (1.f + expf(-lg[k]));
        float p[KC];
        p[0] = 1.f - q[0];
        p[1] = q[0] - q[1];
        p[2] = q[1] - q[2];
        p[3] = q[2] - q[3];
        p[4] = q[3];
        float s = 0.f;
#pragma unroll
        for (int k = 0; k < KC; k++) { p[k] = fmaxf(p[k], EPS_); s += p[k]; }
        s = fmaxf(s, EPS_);
        float inv = 1.f / s;
#pragma unroll
        for (int k = 0; k < KC; k++) p[k] *= inv;

        if (out_size >= B_ * (KM1 + KC)) {
#pragma unroll
            for (int k = 0; k < KM1; k++) out[(size_t)tok * KM1 + k] = lg[k];
#pragma unroll
            for (int k = 0; k < KC; k++)  out[(size_t)B_ * KM1 + (size_t)tok * KC + k] = p[k];
        } else if (out_size == B_ * KC) {
#pragma unroll
            for (int k = 0; k < KC; k++)  out[(size_t)tok * KC + k] = p[k];
        } else {
#pragma unroll
            for (int k = 0; k < KM1; k++) out[(size_t)tok * KM1 + k] = lg[k];
        }
    }
}

// ---------------- launch: exactly 2 kernels, hard-serialized ----------------
extern "C" void kernel_launch(void* const* d_in, const int* in_sizes, int n_in,
                              void* d_out, int out_size) {
    const float* x    = (const float*)d_in[0];
    const int*   sidx = (const int*)  d_in[1];
    const float* W1   = (const float*)d_in[2];
    const float* b1   = (const float*)d_in[3];
    const float* W2   = (const float*)d_in[4];
    const float* b2   = (const float*)d_in[5];
    float*       out  = (float*)d_out;

    static bool init_done = false;
    if (!init_done) {
        cudaFuncSetAttribute(k_gemm1, cudaFuncAttributeMaxDynamicSharedMemorySize, DSMEM_B);
        init_done = true;
    }

    k_prep<<<1 + NXB + NWB, 256>>>(x, W1, sidx);
    k_gemm1<<<dim3(8, B_ / 128, E_), 256, DSMEM_B>>>(b1, W2, b2, out, out_size);
}